// round 17
// baseline (speedup 1.0000x reference)
#include <cuda_runtime.h>
#include <cstdint>

// SpatialGradientLoss3D = mean |sobel3d(pred - target)| over 3 axes.
// R17: R13 (best, 29.2us) with ONE change: ZC 16->32 (z-chunk per block).
// Halves z-halo overhead (34 planes / 32 outputs vs 18/16), halves
// per-block prologue + reduction costs, and gives a single-wave schedule
// (512 blocks @ occ4 on 148 SMs). Everything else byte-identical:
// 4-stage cp.async ring, wait_group 2, h-then-w f32x2 consume, 3-slot
// z-ring, single launch + last-block reduction.
// Shapes fixed: (B=4, C=4, D=64, H=128, W=128), fp32, out = 1 float.

#define D_DIM 64
#define H_DIM 128
#define W_DIM 128
#define HW    (H_DIM * W_DIM)
#define TH 8
#define PR 10
#define ZC 32
#define NP 34                   // planes touched per block (ZC+2)
#define NSTAGE 4
#define PLANE_F4 640            // (P,T) * 10 rows * 32 f4
#define STAGE_BYTES (PLANE_F4 * 16)   // 10240
#define NBLK 512

typedef unsigned long long F2;  // packed f32x2

__device__ __forceinline__ F2 PACK2(float lo, float hi) {
    F2 r; asm("mov.b64 %0,{%1,%2};" : "=l"(r) : "f"(lo), "f"(hi)); return r;
}
__device__ __forceinline__ void UNPACK2(F2 v, float& lo, float& hi) {
    asm("mov.b64 {%0,%1},%2;" : "=f"(lo), "=f"(hi) : "l"(v));
}
__device__ __forceinline__ F2 ADD2(F2 a, F2 b) {
    F2 r; asm("add.rn.f32x2 %0,%1,%2;" : "=l"(r) : "l"(a), "l"(b)); return r;
}
__device__ __forceinline__ F2 SUB2(F2 a, F2 b) {
    F2 r; asm("sub.rn.f32x2 %0,%1,%2;" : "=l"(r) : "l"(a), "l"(b)); return r;
}
__device__ __forceinline__ F2 FMA2(F2 a, F2 b, F2 c) {
    F2 r; asm("fma.rn.f32x2 %0,%1,%2,%3;" : "=l"(r) : "l"(a), "l"(b), "l"(c)); return r;
}
__device__ __forceinline__ F2 ABS2(F2 a) { return a & 0x7FFFFFFF7FFFFFFFULL; }

__device__ __forceinline__ void cpasync16(uint32_t dst, const float* src, int sz) {
    asm volatile("cp.async.cg.shared.global [%0], [%1], 16, %2;\n"
                 :: "r"(dst), "l"(src), "r"(sz) : "memory");
}
__device__ __forceinline__ void cp_commit() {
    asm volatile("cp.async.commit_group;\n" ::: "memory");
}
__device__ __forceinline__ void cp_wait2() {
    asm volatile("cp.async.wait_group 2;\n" ::: "memory");
}

__shared__ float4 sbuf[NSTAGE][PLANE_F4];
__shared__ float wsum_sm[8];

__device__ float g_partials[NBLK];
__device__ unsigned g_count = 0;

// h-then-w consume: plane from ring stage STG into z-slot SLOT.
template<int STG, int SLOT>
__device__ __forceinline__ void plane_consume(int warp, int lane,
                                              F2 (*ss)[2], F2 (*ds)[2], F2 (*sd)[2],
                                              F2 TWO2, bool l0, bool l31) {
    const ulonglong2* sb = reinterpret_cast<const ulonglong2*>(&sbuf[STG][0]);
    F2 e[3][2];
#pragma unroll
    for (int dr = 0; dr < 3; ++dr) {
        ulonglong2 pv = sb[(warp + dr) * 32 + lane];
        ulonglong2 tv = sb[PR * 32 + (warp + dr) * 32 + lane];
        e[dr][0] = SUB2(pv.x, tv.x);
        e[dr][1] = SUB2(pv.y, tv.y);
    }
    F2 hs[2], hd[2];
#pragma unroll
    for (int h = 0; h < 2; ++h) {
        hs[h] = ADD2(FMA2(e[1][h], TWO2, e[0][h]), e[2][h]);
        hd[h] = SUB2(e[2][h], e[0][h]);
    }
    // w-stage on hs
    {
        float s0, s1, s2, s3;
        UNPACK2(hs[0], s0, s1);
        UNPACK2(hs[1], s2, s3);
        float sL = __shfl_up_sync(0xffffffffu, s3, 1);
        float sR = __shfl_down_sync(0xffffffffu, s0, 1);
        if (l0)  sL = 0.f;
        if (l31) sR = 0.f;
        F2 pm  = PACK2(sL, s0);
        F2 p12 = PACK2(s1, s2);
        F2 pr  = PACK2(s3, sR);
        ss[SLOT][0] = ADD2(FMA2(hs[0], TWO2, pm),  p12);
        ss[SLOT][1] = ADD2(FMA2(hs[1], TWO2, p12), pr);
        sd[SLOT][0] = SUB2(p12, pm);
        sd[SLOT][1] = SUB2(pr, p12);
    }
    // w-stage on hd
    {
        float d0, d1, d2, d3;
        UNPACK2(hd[0], d0, d1);
        UNPACK2(hd[1], d2, d3);
        float dL = __shfl_up_sync(0xffffffffu, d3, 1);
        float dR = __shfl_down_sync(0xffffffffu, d0, 1);
        if (l0)  dL = 0.f;
        if (l31) dR = 0.f;
        F2 qm  = PACK2(dL, d0);
        F2 q12 = PACK2(d1, d2);
        F2 qr  = PACK2(d3, dR);
        ds[SLOT][0] = ADD2(FMA2(hd[0], TWO2, qm),  q12);
        ds[SLOT][1] = ADD2(FMA2(hd[1], TWO2, q12), qr);
    }
}

template<int SP>
__device__ __forceinline__ void z_combine(const F2 (*ss)[2], const F2 (*ds)[2],
                                          const F2 (*sd)[2], F2* acc, F2 TWO2) {
    constexpr int SM = (SP + 1) % 3;
    constexpr int S0 = (SP + 2) % 3;
#pragma unroll
    for (int h = 0; h < 2; ++h) {
        F2 gd = SUB2(ss[SP][h], ss[SM][h]);
        F2 gh = ADD2(FMA2(ds[S0][h], TWO2, ds[SM][h]), ds[SP][h]);
        F2 gw = ADD2(FMA2(sd[S0][h], TWO2, sd[SM][h]), sd[SP][h]);
        acc[h] = ADD2(acc[h], ABS2(gd));
        acc[h] = ADD2(acc[h], ABS2(gh));
        acc[h] = ADD2(acc[h], ABS2(gw));
    }
}

__global__ __launch_bounds__(256, 4)
void sg3d_loss_kernel(const float* __restrict__ pred,
                      const float* __restrict__ tgt,
                      float* __restrict__ out) {
    const int tid  = threadIdx.x;
    const int lane = tid & 31;
    const int warp = tid >> 5;
    const bool l0  = (lane == 0);
    const bool l31 = (lane == 31);

    const int h0 = blockIdx.x * TH;
    const int bc = blockIdx.y;
    const int z0 = blockIdx.z * ZC;
    const int bid = blockIdx.x + (blockIdx.y << 4) + (blockIdx.z << 8);

    const size_t base = (size_t)bc * D_DIM * HW;
    const float* P = pred + base;
    const float* T = tgt + base;

    uint32_t smem_base;
    asm("{ .reg .u64 t; cvta.to.shared.u64 t, %1; cvt.u32.u64 %0, t; }"
        : "=r"(smem_base) : "l"((const void*)&sbuf[0][0]));

    // ---- per-slot hoisted params; slot k covers idx = tid + 256k ----
    const float *gp0, *gp1, *gp2;
    int szb0, szb1, szb2;
    const uint32_t saddr0 = smem_base + (uint32_t)tid * 16u;
    {
#pragma unroll
        for (int k = 0; k < 3; ++k) {
            int idx = tid + 256 * k;
            if (idx >= PLANE_F4) idx = PLANE_F4 - 1;   // inert (slot2, tid>=128)
            int a   = idx >= PR * 32;                  // 0=P tile, 1=T tile
            int rel = idx - a * PR * 32;
            int row = rel >> 5;
            int c4  = rel & 31;
            int gh  = h0 - 1 + row;
            int rowok = (unsigned)gh < (unsigned)H_DIM;
            int soff = (rowok ? gh : 0) * W_DIM + c4 * 4;
            const float* p = (a ? T : P) + (ptrdiff_t)(z0 - 1) * HW + soff;
            int sz = rowok ? 16 : 0;
            if (k == 0) { gp0 = p; szb0 = sz; }
            else if (k == 1) { gp1 = p; szb1 = sz; }
            else { gp2 = p; szb2 = sz; }
        }
    }
    const bool act2 = (tid < 128);
    const int zf_ok = (z0 > 0);
    const int zl_ok = (z0 + ZC < D_DIM);

#define ISSUE_PLANE(STAGE, OK)                                                \
    do {                                                                      \
        int m_ = (OK) ? ~0 : 0;                                               \
        cpasync16(saddr0 + (STAGE) * STAGE_BYTES,          gp0, szb0 & m_);   \
        cpasync16(saddr0 + 4096u + (STAGE) * STAGE_BYTES,  gp1, szb1 & m_);   \
        if (act2)                                                             \
            cpasync16(saddr0 + 8192u + (STAGE) * STAGE_BYTES, gp2,            \
                      szb2 & m_);                                             \
        gp0 += HW; gp1 += HW; gp2 += HW;                                      \
    } while (0)

    const F2 TWO2 = 0x4000000040000000ULL;
    F2 ss[3][2], ds[3][2], sd[3][2];
    F2 acc[2] = {0ULL, 0ULL};

    // prologue: planes 0,1,2 -> stages 0,1,2
    ISSUE_PLANE(0, zf_ok); cp_commit();
    ISSUE_PLANE(1, 1);     cp_commit();
    ISSUE_PLANE(2, 1);     cp_commit();

#define STEP(I)                                                               \
    do {                                                                      \
        cp_wait2();                                                           \
        __syncthreads();                                                      \
        if ((I) + 3 < NP)                                                     \
            ISSUE_PLANE(((I) + 3) % NSTAGE,                                   \
                        (((I) + 3) == NP - 1) ? zl_ok : 1);                   \
        cp_commit();                                                          \
        plane_consume<(I) % NSTAGE, (I) % 3>(warp, lane, ss, ds, sd,          \
                                             TWO2, l0, l31);                  \
        if ((I) >= 2) z_combine<(I) % 3>(ss, ds, sd, acc, TWO2);              \
    } while (0)

    STEP(0);  STEP(1);  STEP(2);  STEP(3);  STEP(4);  STEP(5);
    STEP(6);  STEP(7);  STEP(8);  STEP(9);  STEP(10); STEP(11);
    STEP(12); STEP(13); STEP(14); STEP(15); STEP(16); STEP(17);
    STEP(18); STEP(19); STEP(20); STEP(21); STEP(22); STEP(23);
    STEP(24); STEP(25); STEP(26); STEP(27); STEP(28); STEP(29);
    STEP(30); STEP(31); STEP(32); STEP(33);

    // ---- block reduction ----
    float ax, ay, az, aw;
    UNPACK2(acc[0], ax, ay);
    UNPACK2(acc[1], az, aw);
    float a = (ax + ay) + (az + aw);
#pragma unroll
    for (int off = 16; off > 0; off >>= 1)
        a += __shfl_down_sync(0xffffffffu, a, off);

    if (lane == 0) wsum_sm[warp] = a;
    __syncthreads();

    __shared__ bool is_last;
    if (tid == 0) {
        float v = 0.f;
#pragma unroll
        for (int w = 0; w < 8; ++w) v += wsum_sm[w];
        g_partials[bid] = v;
        __threadfence();
        unsigned old = atomicAdd(&g_count, 1u);
        is_last = (old == NBLK - 1);
    }
    __syncthreads();

    if (is_last) {
        __threadfence();
        const volatile float* pv = g_partials;
        float s = 0.f;
#pragma unroll
        for (int k = 0; k < NBLK / 256; ++k)
            s += pv[tid + 256 * k];
#pragma unroll
        for (int off = 16; off > 0; off >>= 1)
            s += __shfl_down_sync(0xffffffffu, s, off);
        if (lane == 0) wsum_sm[warp] = s;
        __syncthreads();
        if (tid == 0) {
            float v = 0.f;
#pragma unroll
            for (int w = 0; w < 8; ++w) v += wsum_sm[w];
            out[0] = v * (1.0f / (3.0f * 16.0f * 64.0f * 128.0f * 128.0f));
            g_count = 0;            // reset for next graph replay
        }
    }
}

extern "C" void kernel_launch(void* const* d_in, const int* in_sizes, int n_in,
                              void* d_out, int out_size) {
    const float* pred = (const float*)d_in[0];
    const float* tgt  = (const float*)d_in[1];
    float* out = (float*)d_out;

    dim3 grid(H_DIM / TH, 16, D_DIM / ZC);   // 16 x 16 x 2 = 512 blocks
    sg3d_loss_kernel<<<grid, 256>>>(pred, tgt, out);
}